// round 3
// baseline (speedup 1.0000x reference)
#include <cuda_runtime.h>
#include <math.h>

// ---------------- problem constants ----------------
#define Bz      512
#define SEQ     65
#define Cc      768
#define Hh      12
#define DHd     64
#define LATd    256
#define NLAYERS 6
#define MTOK    (Bz*SEQ)          // 33280 tokens

// ---------------- scratch (device globals; no allocations) ----------------
__device__ float g_h   [MTOK*Cc];                 // LN output / h2
__device__ float g_qkv [MTOK*3*Cc];               // qkv (q/k normalized in-place)
__device__ float g_attn[Bz*Hh*SEQ*SEQ];           // bias -> logits -> probs
__device__ float g_o   [MTOK*Cc];                 // attention output (B,N,C)
__device__ float g_gate[MTOK*4*Cc];               // gate, then gate*silu(value)
__device__ float g_cls [Bz*Cc];
__device__ float g_lat1[Bz*2*LATd];
__device__ float g_lat2[Bz*Hh*LATd];

// ---------------- SGEMM: C[M,N] = A[M,K] @ B[K,N]  (row-major) ----------------
// EPI=0: C = AB ; EPI=1: C += AB ; EPI=2: C = Gb * silu(AB)
// Requirements: M % 128 == 0, K % 16 == 0. N may be ragged/odd (guarded,
// scalar B loads when Nw % 4 != 0 to avoid misaligned float4).
#define BM 128
#define BN 128
#define BKK 16

template<int EPI>
__global__ __launch_bounds__(256, 2)
void sgemm_k(const float* __restrict__ A, const float* __restrict__ Bw,
             float* __restrict__ Cm, const float* __restrict__ Gb,
             int M, int Nw, int K)
{
    __shared__ float As[BKK][BM];
    __shared__ float Bs[BKK][BN];
    const int tid  = threadIdx.x;
    const int row0 = blockIdx.y * BM;
    const int col0 = blockIdx.x * BN;
    const bool interior = (col0 + BN <= Nw);
    const bool bvec = interior && ((Nw & 3) == 0);   // float4-safe B loads

    const int ty = tid >> 4, tx = tid & 15;
    float acc[8][8];
    #pragma unroll
    for (int i = 0; i < 8; i++)
        #pragma unroll
        for (int j = 0; j < 8; j++) acc[i][j] = 0.f;

    for (int k0 = 0; k0 < K; k0 += BKK) {
        #pragma unroll
        for (int l = 0; l < 2; l++) {
            int f  = tid + l * 256;
            int ar = f >> 2;             // 0..127
            int ac = (f & 3) * 4;        // 0,4,8,12
            float4 av = *(const float4*)(A + (size_t)(row0 + ar) * K + k0 + ac);
            As[ac + 0][ar] = av.x; As[ac + 1][ar] = av.y;
            As[ac + 2][ar] = av.z; As[ac + 3][ar] = av.w;

            int br = f >> 5;             // 0..15
            int bc = (f & 31) * 4;       // 0..124
            const float* bp = Bw + (size_t)(k0 + br) * Nw + col0 + bc;
            if (bvec) {
                float4 bv = *(const float4*)bp;
                Bs[br][bc + 0] = bv.x; Bs[br][bc + 1] = bv.y;
                Bs[br][bc + 2] = bv.z; Bs[br][bc + 3] = bv.w;
            } else {
                #pragma unroll
                for (int u = 0; u < 4; u++)
                    Bs[br][bc + u] = (col0 + bc + u < Nw) ? bp[u] : 0.f;
            }
        }
        __syncthreads();
        #pragma unroll
        for (int k = 0; k < BKK; k++) {
            float a[8], b[8];
            float4 t0 = *(const float4*)&As[k][ty * 8];
            float4 t1 = *(const float4*)&As[k][ty * 8 + 4];
            a[0]=t0.x; a[1]=t0.y; a[2]=t0.z; a[3]=t0.w;
            a[4]=t1.x; a[5]=t1.y; a[6]=t1.z; a[7]=t1.w;
            float4 u0 = *(const float4*)&Bs[k][tx * 8];
            float4 u1 = *(const float4*)&Bs[k][tx * 8 + 4];
            b[0]=u0.x; b[1]=u0.y; b[2]=u0.z; b[3]=u0.w;
            b[4]=u1.x; b[5]=u1.y; b[6]=u1.z; b[7]=u1.w;
            #pragma unroll
            for (int i = 0; i < 8; i++)
                #pragma unroll
                for (int j = 0; j < 8; j++)
                    acc[i][j] += a[i] * b[j];
        }
        __syncthreads();
    }

    #pragma unroll
    for (int i = 0; i < 8; i++) {
        int r = row0 + ty * 8 + i;
        #pragma unroll
        for (int j = 0; j < 8; j++) {
            int c = col0 + tx * 8 + j;
            if (!interior && c >= Nw) continue;
            size_t idx = (size_t)r * Nw + c;
            float v = acc[i][j];
            if (EPI == 1) v += Cm[idx];
            if (EPI == 2) { float sg = 1.f / (1.f + expf(-v)); v = Gb[idx] * (v * sg); }
            Cm[idx] = v;
        }
    }
}

// ---------------- LayerNorm (block per row, 256 threads) ----------------
// MODE 0: plain ; MODE 1: plain + copy row to cls when row%SEQ==0 ; MODE 2: silu(LN)
template<int MODE>
__global__ void ln_k(const float* __restrict__ x, float* __restrict__ out,
                     const float* __restrict__ g, const float* __restrict__ bb,
                     int cols, float* __restrict__ cls)
{
    int row = blockIdx.x;
    const float* xr = x + (size_t)row * cols;
    float s = 0.f, s2 = 0.f;
    for (int c = threadIdx.x; c < cols; c += 256) { float v = xr[c]; s += v; s2 += v * v; }
    #pragma unroll
    for (int off = 16; off; off >>= 1) {
        s  += __shfl_xor_sync(0xffffffffu, s,  off);
        s2 += __shfl_xor_sync(0xffffffffu, s2, off);
    }
    __shared__ float sh[2][8];
    __shared__ float mv[2];
    int w = threadIdx.x >> 5, lane = threadIdx.x & 31;
    if (lane == 0) { sh[0][w] = s; sh[1][w] = s2; }
    __syncthreads();
    if (threadIdx.x == 0) {
        float ts = 0.f, ts2 = 0.f;
        #pragma unroll
        for (int i = 0; i < 8; i++) { ts += sh[0][i]; ts2 += sh[1][i]; }
        float m = ts / cols;
        mv[0] = m;
        mv[1] = rsqrtf(ts2 / cols - m * m + 1e-5f);
    }
    __syncthreads();
    float m = mv[0], inv = mv[1];
    float* outr = out + (size_t)row * cols;
    bool doCls = (MODE == 1) && (row % SEQ == 0);
    float* clsr = doCls ? (cls + (size_t)(row / SEQ) * cols) : nullptr;
    for (int c = threadIdx.x; c < cols; c += 256) {
        float v = (xr[c] - m) * inv * g[c] + bb[c];
        if (MODE == 2) v = v / (1.f + expf(-v));
        outr[c] = v;
        if (doCls) clsr[c] = v;
    }
}

// ---------------- q/k head LayerNorm over DH=64, warp per (token,head,{q,k}) ----------------
__global__ void qkln_k(float* __restrict__ qkv,
                       const float* __restrict__ qg, const float* __restrict__ qb,
                       const float* __restrict__ kg, const float* __restrict__ kb)
{
    int gw = blockIdx.x * 8 + (threadIdx.x >> 5);
    int lane = threadIdx.x & 31;
    if (gw >= MTOK * Hh * 2) return;
    int tok = gw / (Hh * 2);
    int rem = gw % (Hh * 2);
    int hh  = rem >> 1;
    int isK = rem & 1;
    float* p = qkv + (size_t)tok * 2304 + isK * 768 + hh * 64;
    float v0 = p[lane], v1 = p[lane + 32];
    float s = v0 + v1, s2 = v0 * v0 + v1 * v1;
    #pragma unroll
    for (int off = 16; off; off >>= 1) {
        s  += __shfl_xor_sync(0xffffffffu, s,  off);
        s2 += __shfl_xor_sync(0xffffffffu, s2, off);
    }
    float m   = s  * (1.f / 64.f);
    float inv = rsqrtf(s2 * (1.f / 64.f) - m * m + 1e-5f);
    const float* g = isK ? kg : qg;
    const float* b = isK ? kb : qb;
    float sc = isK ? 1.f : 0.125f;        // DH^-0.5 applied to q
    p[lane]      = ((v0 - m) * inv * g[lane]      + b[lane])      * sc;
    p[lane + 32] = ((v1 - m) * inv * g[lane + 32] + b[lane + 32]) * sc;
}

// ---------------- attention logits: attn += q @ k^T (attn holds bias) ----------------
__global__ void attn_scores_k(const float* __restrict__ qkv, float* __restrict__ attn)
{
    __shared__ float qs [SEQ][DHd];
    __shared__ float ksT[DHd][SEQ];
    int b = blockIdx.x / Hh, hh = blockIdx.x % Hh;
    for (int idx = threadIdx.x; idx < SEQ * DHd; idx += 256) {
        int i = idx >> 6, d = idx & 63;
        size_t base = (size_t)(b * SEQ + i) * 2304 + hh * 64 + d;
        qs[i][d]  = qkv[base];
        ksT[d][i] = qkv[base + 768];
    }
    __syncthreads();
    size_t obase = (size_t)blockIdx.x * (SEQ * SEQ);
    for (int oi = threadIdx.x; oi < SEQ * SEQ; oi += 256) {
        int i = oi / SEQ, j = oi - i * SEQ;
        float acc = attn[obase + oi];     // bias
        #pragma unroll
        for (int d = 0; d < DHd; d++) acc += qs[i][d] * ksT[d][j];
        attn[obase + oi] = acc;
    }
}

// ---------------- softmax over rows of 65 (warp per row) ----------------
__global__ void softmax65_k(float* __restrict__ attn, int rows)
{
    int r = blockIdx.x * 8 + (threadIdx.x >> 5);
    if (r >= rows) return;
    int lane = threadIdx.x & 31;
    float* p = attn + (size_t)r * SEQ;
    float v0 = p[lane], v1 = p[lane + 32];
    float v2 = (lane == 0) ? p[64] : -3.4e38f;
    float m = fmaxf(fmaxf(v0, v1), v2);
    #pragma unroll
    for (int off = 16; off; off >>= 1) m = fmaxf(m, __shfl_xor_sync(0xffffffffu, m, off));
    v0 = expf(v0 - m); v1 = expf(v1 - m);
    v2 = (lane == 0) ? expf(v2 - m) : 0.f;
    float s = v0 + v1 + v2;
    #pragma unroll
    for (int off = 16; off; off >>= 1) s += __shfl_xor_sync(0xffffffffu, s, off);
    float inv = 1.f / s;
    p[lane] = v0 * inv; p[lane + 32] = v1 * inv;
    if (lane == 0) p[64] = v2 * inv;
}

// ---------------- o = attn @ v, written as (B,N,C) ----------------
__global__ void attn_av_k(const float* __restrict__ attn, const float* __restrict__ qkv,
                          float* __restrict__ o)
{
    __shared__ float ps[SEQ][SEQ];
    __shared__ float vs[SEQ][DHd];
    int b = blockIdx.x / Hh, hh = blockIdx.x % Hh;
    size_t abase = (size_t)blockIdx.x * (SEQ * SEQ);
    for (int idx = threadIdx.x; idx < SEQ * SEQ; idx += 256)
        ps[idx / SEQ][idx % SEQ] = attn[abase + idx];
    for (int idx = threadIdx.x; idx < SEQ * DHd; idx += 256) {
        int j = idx >> 6, d = idx & 63;
        vs[j][d] = qkv[(size_t)(b * SEQ + j) * 2304 + 1536 + hh * 64 + d];
    }
    __syncthreads();
    for (int oi = threadIdx.x; oi < SEQ * DHd; oi += 256) {
        int i = oi >> 6, d = oi & 63;
        float acc = 0.f;
        #pragma unroll
        for (int j = 0; j < SEQ; j++) acc += ps[i][j] * vs[j][d];
        o[(size_t)(b * SEQ + i) * Cc + hh * 64 + d] = acc;
    }
}

// ---------------- host driver ----------------
extern "C" void kernel_launch(void* const* d_in, const int* in_sizes, int n_in,
                              void* d_out, int out_size)
{
    const float* x      = (const float*)d_in[0];
    const float* ln1_g  = (const float*)d_in[1];
    const float* ln1_b  = (const float*)d_in[2];
    const float* qkv_w  = (const float*)d_in[3];
    const float* proj_w = (const float*)d_in[4];
    const float* qn_g   = (const float*)d_in[5];
    const float* qn_b   = (const float*)d_in[6];
    const float* kn_g   = (const float*)d_in[7];
    const float* kn_b   = (const float*)d_in[8];
    const float* sg_w1  = (const float*)d_in[9];
    const float* sg1_g  = (const float*)d_in[10];
    const float* sg1_b  = (const float*)d_in[11];
    const float* sg_w2  = (const float*)d_in[12];
    const float* sg2_g  = (const float*)d_in[13];
    const float* sg2_b  = (const float*)d_in[14];
    const float* bias_w = (const float*)d_in[15];
    const float* ln2_g  = (const float*)d_in[16];
    const float* ln2_b  = (const float*)d_in[17];
    const float* gate_w = (const float*)d_in[18];
    const float* value_w= (const float*)d_in[19];
    const float* out_w  = (const float*)d_in[20];
    float* xout = (float*)d_out;

    float *h, *qkv, *attn, *o, *gate, *cls, *lat1, *lat2;
    cudaGetSymbolAddress((void**)&h,    g_h);
    cudaGetSymbolAddress((void**)&qkv,  g_qkv);
    cudaGetSymbolAddress((void**)&attn, g_attn);
    cudaGetSymbolAddress((void**)&o,    g_o);
    cudaGetSymbolAddress((void**)&gate, g_gate);
    cudaGetSymbolAddress((void**)&cls,  g_cls);
    cudaGetSymbolAddress((void**)&lat1, g_lat1);
    cudaGetSymbolAddress((void**)&lat2, g_lat2);

    cudaMemcpyAsync(xout, x, (size_t)MTOK * Cc * sizeof(float),
                    cudaMemcpyDeviceToDevice, 0);

    for (int l = 0; l < NLAYERS; l++) {
        const float* L1g = ln1_g  + (size_t)l * Cc;
        const float* L1b = ln1_b  + (size_t)l * Cc;
        const float* Wqkv= qkv_w  + (size_t)l * Cc * 3 * Cc;
        const float* Wpr = proj_w + (size_t)l * Cc * Cc;
        const float* Qg  = qn_g   + (size_t)l * DHd;
        const float* Qb  = qn_b   + (size_t)l * DHd;
        const float* Kg  = kn_g   + (size_t)l * DHd;
        const float* Kb  = kn_b   + (size_t)l * DHd;
        const float* W1  = sg_w1  + (size_t)l * Cc * 2 * LATd;
        const float* S1g = sg1_g  + (size_t)l * 2 * LATd;
        const float* S1b = sg1_b  + (size_t)l * 2 * LATd;
        const float* W2  = sg_w2  + (size_t)l * 2 * LATd * LATd * Hh;
        const float* S2g = sg2_g  + (size_t)l * LATd * Hh;
        const float* S2b = sg2_b  + (size_t)l * LATd * Hh;
        const float* Wb  = bias_w + (size_t)l * LATd * SEQ * SEQ;
        const float* L2g = ln2_g  + (size_t)l * Cc;
        const float* L2b = ln2_b  + (size_t)l * Cc;
        const float* Wg  = gate_w + (size_t)l * Cc * 4 * Cc;
        const float* Wv  = value_w+ (size_t)l * Cc * 4 * Cc;
        const float* Wo  = out_w  + (size_t)l * 4 * Cc * Cc;

        // 1) LN1 (+ cls extraction)
        ln_k<1><<<MTOK, 256>>>(xout, h, L1g, L1b, Cc, cls);
        // 2) qkv = h @ Wqkv   (33280 x 2304 x 768)
        sgemm_k<0><<<dim3(18, 260), 256>>>(h, Wqkv, qkv, nullptr, MTOK, 3 * Cc, Cc);
        // 3) per-head LN on q (with *scale) and k
        qkln_k<<<(MTOK * Hh * 2) / 8, 256>>>(qkv, Qg, Qb, Kg, Kb);
        // 4) cls bias path
        sgemm_k<0><<<dim3(4, 4), 256>>>(cls, W1, lat1, nullptr, Bz, 2 * LATd, Cc);
        ln_k<2><<<Bz, 256>>>(lat1, lat1, S1g, S1b, 2 * LATd, nullptr);      // silu(LN(.))
        sgemm_k<0><<<dim3(24, 4), 256>>>(lat1, W2, lat2, nullptr, Bz, LATd * Hh, 2 * LATd);
        ln_k<0><<<Bz, 256>>>(lat2, lat2, S2g, S2b, LATd * Hh, nullptr);
        // bias logits: (B*H,256)@(256,4225) -> g_attn   (Nw=4225 odd -> scalar B loads)
        sgemm_k<0><<<dim3(34, 48), 256>>>(lat2, Wb, attn, nullptr, Bz * Hh, SEQ * SEQ, LATd);
        // 5) logits += q k^T ; softmax ; o = p v
        attn_scores_k<<<Bz * Hh, 256>>>(qkv, attn);
        softmax65_k<<<(Bz * Hh * SEQ) / 8, 256>>>(attn, Bz * Hh * SEQ);
        attn_av_k<<<Bz * Hh, 256>>>(attn, qkv, o);
        // 6) x += o @ Wproj
        sgemm_k<1><<<dim3(6, 260), 256>>>(o, Wpr, xout, nullptr, MTOK, Cc, Cc);
        // 7) LN2
        ln_k<0><<<MTOK, 256>>>(xout, h, L2g, L2b, Cc, nullptr);
        // 8) MLP: gate = h@Wg ; gate *= silu(h@Wv) ; x += gate @ Wo
        sgemm_k<0><<<dim3(24, 260), 256>>>(h, Wg, gate, nullptr, MTOK, 4 * Cc, Cc);
        sgemm_k<2><<<dim3(24, 260), 256>>>(h, Wv, gate, gate, MTOK, 4 * Cc, Cc);
        sgemm_k<1><<<dim3(6, 260), 256>>>(gate, Wo, xout, nullptr, MTOK, Cc, 4 * Cc);
    }
}

// round 7
// speedup vs baseline: 2.3955x; 2.3955x over previous
#include <cuda_runtime.h>
#include <math.h>
#include <stdint.h>

// ---------------- problem constants ----------------
#define Bz      512
#define SEQ     65
#define Cc      768
#define Hh      12
#define DHd     64
#define LATd    256
#define NLAYERS 6
#define MTOK    (Bz*SEQ)          // 33280 tokens

// ---------------- scratch (device globals; no allocations) ----------------
__device__ float g_h   [MTOK*Cc];
__device__ float g_qkv [MTOK*3*Cc];
__device__ float g_attn[Bz*Hh*SEQ*SEQ];
__device__ float g_o   [MTOK*Cc];
__device__ float g_gate[MTOK*4*Cc];
__device__ float g_cls [Bz*Cc];
__device__ float g_lat1[Bz*2*LATd];
__device__ float g_lat2[Bz*Hh*LATd];

// ---------------- TF32 helpers ----------------
__device__ __forceinline__ float to_tf32(float x) {
    float r;
    asm("cvt.rna.tf32.f32 %0, %1;" : "=f"(r) : "f"(x));
    return r;
}
__device__ __forceinline__ float4 to_tf32x4(float4 v) {
    v.x = to_tf32(v.x); v.y = to_tf32(v.y); v.z = to_tf32(v.z); v.w = to_tf32(v.w);
    return v;
}
__device__ __forceinline__ void mma_tf32(float4& d, const float a0, const float a1,
                                         const float a2, const float a3,
                                         const float b0, const float b1) {
    asm volatile(
        "mma.sync.aligned.m16n8k8.row.col.f32.tf32.tf32.f32 "
        "{%0,%1,%2,%3}, {%4,%5,%6,%7}, {%8,%9}, {%0,%1,%2,%3};"
        : "+f"(d.x), "+f"(d.y), "+f"(d.z), "+f"(d.w)
        : "r"(__float_as_uint(a0)), "r"(__float_as_uint(a1)),
          "r"(__float_as_uint(a2)), "r"(__float_as_uint(a3)),
          "r"(__float_as_uint(b0)), "r"(__float_as_uint(b1)));
}

// ---------------- TF32 GEMM: C[M,N] = A[M,K] @ B[K,N] (row-major) --------
// EPI=0: C = AB ; EPI=1: C += AB ; EPI=2: C = Gb * silu(AB)
// M % 128 == 0, K % 16 == 0, N arbitrary (guarded; scalar B loads if ragged).
#define BM 128
#define BN 128
#define BKK 16
#define PA 20     // As row pad: [128][20], bank=(20g+t)%32 conflict-free
#define PB 136    // Bs row pad: [16][136], 136%32==8 -> bank=(8t+g)%32 conflict-free

template<int EPI>
__global__ __launch_bounds__(256, 2)
void gemm_tf32_k(const float* __restrict__ A, const float* __restrict__ Bw,
                 float* __restrict__ Cm, const float* __restrict__ Gb,
                 int M, int Nw, int K)
{
    __shared__ float As[BM][PA];   // [m][k]
    __shared__ float Bs[BKK][PB];  // [k][n]

    const int tid  = threadIdx.x;
    const int row0 = blockIdx.y * BM;
    const int col0 = blockIdx.x * BN;
    const bool interior = (col0 + BN <= Nw);
    const bool bvec = interior && ((Nw & 3) == 0);

    const int lane = tid & 31, g = lane >> 2, t = lane & 3;
    const int wid = tid >> 5, wm = wid & 1, wn = wid >> 1;
    const int m0w = wm * 64, n0w = wn * 32;

    // per-thread staging indices (2 chunks of 256 threads each)
    const int ar0 = tid >> 2,            ac0 = (tid & 3) * 4;
    const int ar1 = (tid + 256) >> 2,    ac1 = (tid & 3) * 4;   // f&3 same
    const int br0 = tid >> 5,            bc0 = (tid & 31) * 4;
    const int br1 = (tid + 256) >> 5,    bc1 = (tid & 31) * 4;

    float4 acc[4][4];
    #pragma unroll
    for (int i = 0; i < 4; i++)
        #pragma unroll
        for (int j = 0; j < 4; j++) acc[i][j] = make_float4(0.f, 0.f, 0.f, 0.f);

    float4 aR[2], bR[2];

    // ---- global load of tile at k0 into regs ----
    auto load_tile = [&](int k0) {
        aR[0] = *(const float4*)(A + (size_t)(row0 + ar0) * K + k0 + ac0);
        aR[1] = *(const float4*)(A + (size_t)(row0 + ar1) * K + k0 + ac1);
        if (bvec) {
            bR[0] = *(const float4*)(Bw + (size_t)(k0 + br0) * Nw + col0 + bc0);
            bR[1] = *(const float4*)(Bw + (size_t)(k0 + br1) * Nw + col0 + bc1);
        } else {
            const float* p0 = Bw + (size_t)(k0 + br0) * Nw + col0 + bc0;
            const float* p1 = Bw + (size_t)(k0 + br1) * Nw + col0 + bc1;
            float v0[4], v1[4];
            #pragma unroll
            for (int u = 0; u < 4; u++) {
                v0[u] = (col0 + bc0 + u < Nw) ? p0[u] : 0.f;
                v1[u] = (col0 + bc1 + u < Nw) ? p1[u] : 0.f;
            }
            bR[0] = make_float4(v0[0], v0[1], v0[2], v0[3]);
            bR[1] = make_float4(v1[0], v1[1], v1[2], v1[3]);
        }
    };

    load_tile(0);

    for (int k0 = 0; k0 < K; k0 += BKK) {
        // store staged regs to smem (convert to tf32)
        *(float4*)&As[ar0][ac0] = to_tf32x4(aR[0]);
        *(float4*)&As[ar1][ac1] = to_tf32x4(aR[1]);
        *(float4*)&Bs[br0][bc0] = to_tf32x4(bR[0]);
        *(float4*)&Bs[br1][bc1] = to_tf32x4(bR[1]);
        __syncthreads();

        if (k0 + BKK < K) load_tile(k0 + BKK);

        #pragma unroll
        for (int ks = 0; ks < BKK; ks += 8) {
            float av[4][4], bv[4][2];
            #pragma unroll
            for (int mt = 0; mt < 4; mt++) {
                int m = m0w + mt * 16 + g;
                av[mt][0] = As[m    ][ks + t];
                av[mt][1] = As[m + 8][ks + t];
                av[mt][2] = As[m    ][ks + t + 4];
                av[mt][3] = As[m + 8][ks + t + 4];
            }
            #pragma unroll
            for (int nt = 0; nt < 4; nt++) {
                int n = n0w + nt * 8 + g;
                bv[nt][0] = Bs[ks + t    ][n];
                bv[nt][1] = Bs[ks + t + 4][n];
            }
            #pragma unroll
            for (int mt = 0; mt < 4; mt++)
                #pragma unroll
                for (int nt = 0; nt < 4; nt++)
                    mma_tf32(acc[mt][nt], av[mt][0], av[mt][1], av[mt][2], av[mt][3],
                             bv[nt][0], bv[nt][1]);
        }
        __syncthreads();
    }

    // ---- epilogue ----
    #pragma unroll
    for (int mt = 0; mt < 4; mt++) {
        int r0 = row0 + m0w + mt * 16 + g;
        #pragma unroll
        for (int nt = 0; nt < 4; nt++) {
            int c0 = col0 + n0w + nt * 8 + t * 2;
            float vals[4] = {acc[mt][nt].x, acc[mt][nt].y, acc[mt][nt].z, acc[mt][nt].w};
            #pragma unroll
            for (int e = 0; e < 4; e++) {
                int r = r0 + ((e >= 2) ? 8 : 0);
                int c = c0 + (e & 1);
                if (!interior && c >= Nw) continue;
                size_t idx = (size_t)r * Nw + c;
                float v = vals[e];
                if (EPI == 1) v += Cm[idx];
                if (EPI == 2) { float sg = 1.f / (1.f + expf(-v)); v = Gb[idx] * (v * sg); }
                Cm[idx] = v;
            }
        }
    }
}

// ---------------- LayerNorm (block per row, 256 threads) ----------------
template<int MODE>
__global__ void ln_k(const float* __restrict__ x, float* __restrict__ out,
                     const float* __restrict__ g, const float* __restrict__ bb,
                     int cols, float* __restrict__ cls)
{
    int row = blockIdx.x;
    const float* xr = x + (size_t)row * cols;
    float s = 0.f, s2 = 0.f;
    for (int c = threadIdx.x; c < cols; c += 256) { float v = xr[c]; s += v; s2 += v * v; }
    #pragma unroll
    for (int off = 16; off; off >>= 1) {
        s  += __shfl_xor_sync(0xffffffffu, s,  off);
        s2 += __shfl_xor_sync(0xffffffffu, s2, off);
    }
    __shared__ float sh[2][8];
    __shared__ float mv[2];
    int w = threadIdx.x >> 5, lane = threadIdx.x & 31;
    if (lane == 0) { sh[0][w] = s; sh[1][w] = s2; }
    __syncthreads();
    if (threadIdx.x == 0) {
        float ts = 0.f, ts2 = 0.f;
        #pragma unroll
        for (int i = 0; i < 8; i++) { ts += sh[0][i]; ts2 += sh[1][i]; }
        float m = ts / cols;
        mv[0] = m;
        mv[1] = rsqrtf(ts2 / cols - m * m + 1e-5f);
    }
    __syncthreads();
    float m = mv[0], inv = mv[1];
    float* outr = out + (size_t)row * cols;
    bool doCls = (MODE == 1) && (row % SEQ == 0);
    float* clsr = doCls ? (cls + (size_t)(row / SEQ) * cols) : nullptr;
    for (int c = threadIdx.x; c < cols; c += 256) {
        float v = (xr[c] - m) * inv * g[c] + bb[c];
        if (MODE == 2) v = v / (1.f + expf(-v));
        outr[c] = v;
        if (doCls) clsr[c] = v;
    }
}

// ---------------- q/k head LayerNorm ----------------
__global__ void qkln_k(float* __restrict__ qkv,
                       const float* __restrict__ qg, const float* __restrict__ qb,
                       const float* __restrict__ kg, const float* __restrict__ kb)
{
    int gw = blockIdx.x * 8 + (threadIdx.x >> 5);
    int lane = threadIdx.x & 31;
    if (gw >= MTOK * Hh * 2) return;
    int tok = gw / (Hh * 2);
    int rem = gw % (Hh * 2);
    int hh  = rem >> 1;
    int isK = rem & 1;
    float* p = qkv + (size_t)tok * 2304 + isK * 768 + hh * 64;
    float v0 = p[lane], v1 = p[lane + 32];
    float s = v0 + v1, s2 = v0 * v0 + v1 * v1;
    #pragma unroll
    for (int off = 16; off; off >>= 1) {
        s  += __shfl_xor_sync(0xffffffffu, s,  off);
        s2 += __shfl_xor_sync(0xffffffffu, s2, off);
    }
    float m   = s  * (1.f / 64.f);
    float inv = rsqrtf(s2 * (1.f / 64.f) - m * m + 1e-5f);
    const float* g = isK ? kg : qg;
    const float* b = isK ? kb : qb;
    float sc = isK ? 1.f : 0.125f;
    p[lane]      = ((v0 - m) * inv * g[lane]      + b[lane])      * sc;
    p[lane + 32] = ((v1 - m) * inv * g[lane + 32] + b[lane + 32]) * sc;
}

// ---------------- attention logits: attn += q @ k^T ----------------
__global__ void attn_scores_k(const float* __restrict__ qkv, float* __restrict__ attn)
{
    __shared__ float qs [SEQ][DHd];
    __shared__ float ksT[DHd][SEQ];
    int b = blockIdx.x / Hh, hh = blockIdx.x % Hh;
    for (int idx = threadIdx.x; idx < SEQ * DHd; idx += 256) {
        int i = idx >> 6, d = idx & 63;
        size_t base = (size_t)(b * SEQ + i) * 2304 + hh * 64 + d;
        qs[i][d]  = qkv[base];
        ksT[d][i] = qkv[base + 768];
    }
    __syncthreads();
    size_t obase = (size_t)blockIdx.x * (SEQ * SEQ);
    for (int oi = threadIdx.x; oi < SEQ * SEQ; oi += 256) {
        int i = oi / SEQ, j = oi - i * SEQ;
        float acc = attn[obase + oi];
        #pragma unroll
        for (int d = 0; d < DHd; d++) acc += qs[i][d] * ksT[d][j];
        attn[obase + oi] = acc;
    }
}

// ---------------- softmax over rows of 65 ----------------
__global__ void softmax65_k(float* __restrict__ attn, int rows)
{
    int r = blockIdx.x * 8 + (threadIdx.x >> 5);
    if (r >= rows) return;
    int lane = threadIdx.x & 31;
    float* p = attn + (size_t)r * SEQ;
    float v0 = p[lane], v1 = p[lane + 32];
    float v2 = (lane == 0) ? p[64] : -3.4e38f;
    float m = fmaxf(fmaxf(v0, v1), v2);
    #pragma unroll
    for (int off = 16; off; off >>= 1) m = fmaxf(m, __shfl_xor_sync(0xffffffffu, m, off));
    v0 = expf(v0 - m); v1 = expf(v1 - m);
    v2 = (lane == 0) ? expf(v2 - m) : 0.f;
    float s = v0 + v1 + v2;
    #pragma unroll
    for (int off = 16; off; off >>= 1) s += __shfl_xor_sync(0xffffffffu, s, off);
    float inv = 1.f / s;
    p[lane] = v0 * inv; p[lane + 32] = v1 * inv;
    if (lane == 0) p[64] = v2 * inv;
}

// ---------------- o = attn @ v ----------------
__global__ void attn_av_k(const float* __restrict__ attn, const float* __restrict__ qkv,
                          float* __restrict__ o)
{
    __shared__ float ps[SEQ][SEQ];
    __shared__ float vs[SEQ][DHd];
    int b = blockIdx.x / Hh, hh = blockIdx.x % Hh;
    size_t abase = (size_t)blockIdx.x * (SEQ * SEQ);
    for (int idx = threadIdx.x; idx < SEQ * SEQ; idx += 256)
        ps[idx / SEQ][idx % SEQ] = attn[abase + idx];
    for (int idx = threadIdx.x; idx < SEQ * DHd; idx += 256) {
        int j = idx >> 6, d = idx & 63;
        vs[j][d] = qkv[(size_t)(b * SEQ + j) * 2304 + 1536 + hh * 64 + d];
    }
    __syncthreads();
    for (int oi = threadIdx.x; oi < SEQ * DHd; oi += 256) {
        int i = oi >> 6, d = oi & 63;
        float acc = 0.f;
        #pragma unroll
        for (int j = 0; j < SEQ; j++) acc += ps[i][j] * vs[j][d];
        o[(size_t)(b * SEQ + i) * Cc + hh * 64 + d] = acc;
    }
}

// ---------------- host driver ----------------
extern "C" void kernel_launch(void* const* d_in, const int* in_sizes, int n_in,
                              void* d_out, int out_size)
{
    const float* x      = (const float*)d_in[0];
    const float* ln1_g  = (const float*)d_in[1];
    const float* ln1_b  = (const float*)d_in[2];
    const float* qkv_w  = (const float*)d_in[3];
    const float* proj_w = (const float*)d_in[4];
    const float* qn_g   = (const float*)d_in[5];
    const float* qn_b   = (const float*)d_in[6];
    const float* kn_g   = (const float*)d_in[7];
    const float* kn_b   = (const float*)d_in[8];
    const float* sg_w1  = (const float*)d_in[9];
    const float* sg1_g  = (const float*)d_in[10];
    const float* sg1_b  = (const float*)d_in[11];
    const float* sg_w2  = (const float*)d_in[12];
    const float* sg2_g  = (const float*)d_in[13];
    const float* sg2_b  = (const float*)d_in[14];
    const float* bias_w = (const float*)d_in[15];
    const float* ln2_g  = (const float*)d_in[16];
    const float* ln2_b  = (const float*)d_in[17];
    const float* gate_w = (const float*)d_in[18];
    const float* value_w= (const float*)d_in[19];
    const float* out_w  = (const float*)d_in[20];
    float* xout = (float*)d_out;

    float *h, *qkv, *attn, *o, *gate, *cls, *lat1, *lat2;
    cudaGetSymbolAddress((void**)&h,    g_h);
    cudaGetSymbolAddress((void**)&qkv,  g_qkv);
    cudaGetSymbolAddress((void**)&attn, g_attn);
    cudaGetSymbolAddress((void**)&o,    g_o);
    cudaGetSymbolAddress((void**)&gate, g_gate);
    cudaGetSymbolAddress((void**)&cls,  g_cls);
    cudaGetSymbolAddress((void**)&lat1, g_lat1);
    cudaGetSymbolAddress((void**)&lat2, g_lat2);

    cudaMemcpyAsync(xout, x, (size_t)MTOK * Cc * sizeof(float),
                    cudaMemcpyDeviceToDevice, 0);

    for (int l = 0; l < NLAYERS; l++) {
        const float* L1g = ln1_g  + (size_t)l * Cc;
        const float* L1b = ln1_b  + (size_t)l * Cc;
        const float* Wqkv= qkv_w  + (size_t)l * Cc * 3 * Cc;
        const float* Wpr = proj_w + (size_t)l * Cc * Cc;
        const float* Qg  = qn_g   + (size_t)l * DHd;
        const float* Qb  = qn_b   + (size_t)l * DHd;
        const float* Kg  = kn_g   + (size_t)l * DHd;
        const float* Kb  = kn_b   + (size_t)l * DHd;
        const float* W1  = sg_w1  + (size_t)l * Cc * 2 * LATd;
        const float* S1g = sg1_g  + (size_t)l * 2 * LATd;
        const float* S1b = sg1_b  + (size_t)l * 2 * LATd;
        const float* W2  = sg_w2  + (size_t)l * 2 * LATd * LATd * Hh;
        const float* S2g = sg2_g  + (size_t)l * LATd * Hh;
        const float* S2b = sg2_b  + (size_t)l * LATd * Hh;
        const float* Wb  = bias_w + (size_t)l * LATd * SEQ * SEQ;
        const float* L2g = ln2_g  + (size_t)l * Cc;
        const float* L2b = ln2_b  + (size_t)l * Cc;
        const float* Wg  = gate_w + (size_t)l * Cc * 4 * Cc;
        const float* Wv  = value_w+ (size_t)l * Cc * 4 * Cc;
        const float* Wo  = out_w  + (size_t)l * 4 * Cc * Cc;

        // 1) LN1 (+ cls extraction)
        ln_k<1><<<MTOK, 256>>>(xout, h, L1g, L1b, Cc, cls);
        // 2) qkv = h @ Wqkv
        gemm_tf32_k<0><<<dim3(18, 260), 256>>>(h, Wqkv, qkv, nullptr, MTOK, 3 * Cc, Cc);
        // 3) per-head LN on q (with *scale) and k
        qkln_k<<<(MTOK * Hh * 2) / 8, 256>>>(qkv, Qg, Qb, Kg, Kb);
        // 4) cls bias path
        gemm_tf32_k<0><<<dim3(4, 4), 256>>>(cls, W1, lat1, nullptr, Bz, 2 * LATd, Cc);
        ln_k<2><<<Bz, 256>>>(lat1, lat1, S1g, S1b, 2 * LATd, nullptr);
        gemm_tf32_k<0><<<dim3(24, 4), 256>>>(lat1, W2, lat2, nullptr, Bz, LATd * Hh, 2 * LATd);
        ln_k<0><<<Bz, 256>>>(lat2, lat2, S2g, S2b, LATd * Hh, nullptr);
        // bias logits: (B*H,256)@(256,4225) -> g_attn (ragged N)
        gemm_tf32_k<0><<<dim3(34, 48), 256>>>(lat2, Wb, attn, nullptr, Bz * Hh, SEQ * SEQ, LATd);
        // 5) logits += q k^T ; softmax ; o = p v
        attn_scores_k<<<Bz * Hh, 256>>>(qkv, attn);
        softmax65_k<<<(Bz * Hh * SEQ) / 8, 256>>>(attn, Bz * Hh * SEQ);
        attn_av_k<<<Bz * Hh, 256>>>(attn, qkv, o);
        // 6) x += o @ Wproj
        gemm_tf32_k<1><<<dim3(6, 260), 256>>>(o, Wpr, xout, nullptr, MTOK, Cc, Cc);
        // 7) LN2
        ln_k<0><<<MTOK, 256>>>(xout, h, L2g, L2b, Cc, nullptr);
        // 8) MLP
        gemm_tf32_k<0><<<dim3(24, 260), 256>>>(h, Wg, gate, nullptr, MTOK, 4 * Cc, Cc);
        gemm_tf32_k<2><<<dim3(24, 260), 256>>>(h, Wv, gate, gate, MTOK, 4 * Cc, Cc);
        gemm_tf32_k<1><<<dim3(6, 260), 256>>>(gate, Wo, xout, nullptr, MTOK, Cc, 4 * Cc);
    }
}

// round 10
// speedup vs baseline: 2.7343x; 1.1414x over previous
#include <cuda_runtime.h>
#include <math.h>
#include <stdint.h>

// ---------------- problem constants ----------------
#define Bz      512
#define SEQ     65
#define Cc      768
#define Hh      12
#define DHd     64
#define LATd    256
#define NLAYERS 6
#define MTOK    (Bz*SEQ)          // 33280 tokens

// ---------------- scratch (device globals; no allocations) ----------------
__device__ float g_h   [MTOK*Cc];
__device__ float g_qkv [MTOK*3*Cc];
__device__ float g_attn[Bz*Hh*SEQ*SEQ];
__device__ float g_o   [MTOK*Cc];
__device__ float g_gate[MTOK*4*Cc];
__device__ float g_cls [Bz*Cc];
__device__ float g_lat1[Bz*2*LATd];
__device__ float g_lat2[Bz*Hh*LATd];

// tf32-preconverted weights (all 6 layers, concatenated)
#define W_QKV_OFF   0
#define W_QKV_SZ    (NLAYERS*Cc*3*Cc)            // 10,616,832
#define W_PROJ_OFF  (W_QKV_OFF + W_QKV_SZ)
#define W_PROJ_SZ   (NLAYERS*Cc*Cc)              // 3,538,944
#define W_W1_OFF    (W_PROJ_OFF + W_PROJ_SZ)
#define W_W1_SZ     (NLAYERS*Cc*2*LATd)          // 2,359,296
#define W_W2_OFF    (W_W1_OFF + W_W1_SZ)
#define W_W2_SZ     (NLAYERS*2*LATd*LATd*Hh)     // 9,437,184
#define W_GATE_OFF  (W_W2_OFF + W_W2_SZ)
#define W_GATE_SZ   (NLAYERS*Cc*4*Cc)            // 14,155,776
#define W_VAL_OFF   (W_GATE_OFF + W_GATE_SZ)
#define W_VAL_SZ    (NLAYERS*Cc*4*Cc)
#define W_OUT_OFF   (W_VAL_OFF + W_VAL_SZ)
#define W_OUT_SZ    (NLAYERS*4*Cc*Cc)
#define W_TOTAL     (W_OUT_OFF + W_OUT_SZ)       // 68,419,584 floats
__device__ float g_wtf[W_TOTAL];

// ---------------- TF32 helpers ----------------
__device__ __forceinline__ float to_tf32(float x) {
    float r;
    asm("cvt.rna.tf32.f32 %0, %1;" : "=f"(r) : "f"(x));
    return r;
}
__device__ __forceinline__ void mma_tf32(float4& d, const float a0, const float a1,
                                         const float a2, const float a3,
                                         const float b0, const float b1) {
    asm volatile(
        "mma.sync.aligned.m16n8k8.row.col.f32.tf32.tf32.f32 "
        "{%0,%1,%2,%3}, {%4,%5,%6,%7}, {%8,%9}, {%0,%1,%2,%3};"
        : "+f"(d.x), "+f"(d.y), "+f"(d.z), "+f"(d.w)
        : "r"(__float_as_uint(a0)), "r"(__float_as_uint(a1)),
          "r"(__float_as_uint(a2)), "r"(__float_as_uint(a3)),
          "r"(__float_as_uint(b0)), "r"(__float_as_uint(b1)));
}
__device__ __forceinline__ void cp_async16(uint32_t smem, const void* gptr) {
    asm volatile("cp.async.cg.shared.global [%0], [%1], 16;\n"
                 :: "r"(smem), "l"(gptr));
}

// weight cvt: out[i] = tf32(in[i]), n % 4 == 0
__global__ void wcvt_k(const float* __restrict__ in, float* __restrict__ out, int n4)
{
    int i = blockIdx.x * blockDim.x + threadIdx.x;
    if (i >= n4) return;
    float4 v = ((const float4*)in)[i];
    v.x = to_tf32(v.x); v.y = to_tf32(v.y); v.z = to_tf32(v.z); v.w = to_tf32(v.w);
    ((float4*)out)[i] = v;
}

// ---------------- pipelined TF32 GEMM (aligned N, pre-tf32 inputs) --------
// C[M,N] = A[M,K] @ B[K,N] row-major.  EPI=0: C=AB ; 1: C+=AB ; 2: C=tf32(Gb*silu(AB))
// M%128==0, K%16==0, N%128==0. A and B must already be tf32-rounded.
#define BM 128
#define BN 128
#define BKK 16
#define PA 20     // As row pad (floats): 80B rows, 16B aligned
#define PB 136    // Bs row pad: 544B rows

template<int EPI>
__global__ __launch_bounds__(256, 2)
void gemm_pipe_k(const float* __restrict__ A, const float* __restrict__ Bw,
                 float* __restrict__ Cm, const float* __restrict__ Gb,
                 int M, int Nw, int K)
{
    __shared__ float As[2][BM][PA];
    __shared__ float Bs[2][BKK][PB];

    const int tid  = threadIdx.x;
    const int row0 = blockIdx.y * BM;
    const int col0 = blockIdx.x * BN;

    const int lane = tid & 31, g = lane >> 2, t = lane & 3;
    const int wid = tid >> 5, wm = wid & 1, wn = wid >> 1;
    const int m0w = wm * 64, n0w = wn * 32;

    const int ar0 = tid >> 2,         ac0 = (tid & 3) * 4;
    const int ar1 = (tid + 256) >> 2;                          // ac same
    const int br0 = tid >> 5,         bc0 = (tid & 31) * 4;
    const int br1 = (tid + 256) >> 5;

    float4 acc[4][4];
    #pragma unroll
    for (int i = 0; i < 4; i++)
        #pragma unroll
        for (int j = 0; j < 4; j++) acc[i][j] = make_float4(0.f, 0.f, 0.f, 0.f);

    auto load_stage = [&](int s, int k0) {
        cp_async16((uint32_t)__cvta_generic_to_shared(&As[s][ar0][ac0]),
                   A + (size_t)(row0 + ar0) * K + k0 + ac0);
        cp_async16((uint32_t)__cvta_generic_to_shared(&As[s][ar1][ac0]),
                   A + (size_t)(row0 + ar1) * K + k0 + ac0);
        cp_async16((uint32_t)__cvta_generic_to_shared(&Bs[s][br0][bc0]),
                   Bw + (size_t)(k0 + br0) * Nw + col0 + bc0);
        cp_async16((uint32_t)__cvta_generic_to_shared(&Bs[s][br1][bc0]),
                   Bw + (size_t)(k0 + br1) * Nw + col0 + bc0);
        asm volatile("cp.async.commit_group;\n");
    };

    const int nk = K / BKK;
    load_stage(0, 0);

    for (int it = 0; it < nk; it++) {
        if (it + 1 < nk) {
            load_stage((it + 1) & 1, (it + 1) * BKK);
            asm volatile("cp.async.wait_group 1;\n");
        } else {
            asm volatile("cp.async.wait_group 0;\n");
        }
        __syncthreads();

        const int s = it & 1;
        #pragma unroll
        for (int ks = 0; ks < BKK; ks += 8) {
            float av[4][4], bv[4][2];
            #pragma unroll
            for (int mt = 0; mt < 4; mt++) {
                int m = m0w + mt * 16 + g;
                av[mt][0] = As[s][m    ][ks + t];
                av[mt][1] = As[s][m + 8][ks + t];
                av[mt][2] = As[s][m    ][ks + t + 4];
                av[mt][3] = As[s][m + 8][ks + t + 4];
            }
            #pragma unroll
            for (int nt = 0; nt < 4; nt++) {
                int n = n0w + nt * 8 + g;
                bv[nt][0] = Bs[s][ks + t    ][n];
                bv[nt][1] = Bs[s][ks + t + 4][n];
            }
            #pragma unroll
            for (int mt = 0; mt < 4; mt++)
                #pragma unroll
                for (int nt = 0; nt < 4; nt++)
                    mma_tf32(acc[mt][nt], av[mt][0], av[mt][1], av[mt][2], av[mt][3],
                             bv[nt][0], bv[nt][1]);
        }
        __syncthreads();
    }

    #pragma unroll
    for (int mt = 0; mt < 4; mt++) {
        int r0 = row0 + m0w + mt * 16 + g;
        #pragma unroll
        for (int nt = 0; nt < 4; nt++) {
            int c0 = col0 + n0w + nt * 8 + t * 2;
            float vals[4] = {acc[mt][nt].x, acc[mt][nt].y, acc[mt][nt].z, acc[mt][nt].w};
            #pragma unroll
            for (int e = 0; e < 4; e++) {
                int r = r0 + ((e >= 2) ? 8 : 0);
                int c = c0 + (e & 1);
                size_t idx = (size_t)r * Nw + c;
                float v = vals[e];
                if (EPI == 1) v += Cm[idx];
                if (EPI == 2) {
                    float sg = 1.f / (1.f + expf(-v));
                    v = to_tf32(Gb[idx] * (v * sg));   // A of the next GEMM
                }
                Cm[idx] = v;
            }
        }
    }
}

// ---------------- legacy GEMM (ragged N; converts in-kernel) -------------
template<int EPI>
__global__ __launch_bounds__(256, 2)
void gemm_tf32_k(const float* __restrict__ A, const float* __restrict__ Bw,
                 float* __restrict__ Cm, const float* __restrict__ Gb,
                 int M, int Nw, int K)
{
    __shared__ float As[BM][PA];
    __shared__ float Bs[BKK][PB];
    const int tid  = threadIdx.x;
    const int row0 = blockIdx.y * BM;
    const int col0 = blockIdx.x * BN;
    const bool interior = (col0 + BN <= Nw);
    const bool bvec = interior && ((Nw & 3) == 0);

    const int lane = tid & 31, g = lane >> 2, t = lane & 3;
    const int wid = tid >> 5, wm = wid & 1, wn = wid >> 1;
    const int m0w = wm * 64, n0w = wn * 32;

    const int ar0 = tid >> 2,         ac0 = (tid & 3) * 4;
    const int ar1 = (tid + 256) >> 2;
    const int br0 = tid >> 5,         bc0 = (tid & 31) * 4;
    const int br1 = (tid + 256) >> 5;

    float4 acc[4][4];
    #pragma unroll
    for (int i = 0; i < 4; i++)
        #pragma unroll
        for (int j = 0; j < 4; j++) acc[i][j] = make_float4(0.f, 0.f, 0.f, 0.f);

    float4 aR[2], bR[2];
    auto cvt4 = [](float4 v) {
        v.x = to_tf32(v.x); v.y = to_tf32(v.y); v.z = to_tf32(v.z); v.w = to_tf32(v.w);
        return v;
    };
    auto load_tile = [&](int k0) {
        aR[0] = *(const float4*)(A + (size_t)(row0 + ar0) * K + k0 + ac0);
        aR[1] = *(const float4*)(A + (size_t)(row0 + ar1) * K + k0 + ac0);
        if (bvec) {
            bR[0] = *(const float4*)(Bw + (size_t)(k0 + br0) * Nw + col0 + bc0);
            bR[1] = *(const float4*)(Bw + (size_t)(k0 + br1) * Nw + col0 + bc0);
        } else {
            const float* p0 = Bw + (size_t)(k0 + br0) * Nw + col0 + bc0;
            const float* p1 = Bw + (size_t)(k0 + br1) * Nw + col0 + bc0;
            float v0[4], v1[4];
            #pragma unroll
            for (int u = 0; u < 4; u++) {
                v0[u] = (col0 + bc0 + u < Nw) ? p0[u] : 0.f;
                v1[u] = (col0 + bc0 + u < Nw) ? p1[u] : 0.f;
            }
            bR[0] = make_float4(v0[0], v0[1], v0[2], v0[3]);
            bR[1] = make_float4(v1[0], v1[1], v1[2], v1[3]);
        }
    };

    load_tile(0);
    for (int k0 = 0; k0 < K; k0 += BKK) {
        *(float4*)&As[ar0][ac0] = cvt4(aR[0]);
        *(float4*)&As[ar1][ac0] = cvt4(aR[1]);
        *(float4*)&Bs[br0][bc0] = cvt4(bR[0]);
        *(float4*)&Bs[br1][bc0] = cvt4(bR[1]);
        __syncthreads();
        if (k0 + BKK < K) load_tile(k0 + BKK);
        #pragma unroll
        for (int ks = 0; ks < BKK; ks += 8) {
            float av[4][4], bv[4][2];
            #pragma unroll
            for (int mt = 0; mt < 4; mt++) {
                int m = m0w + mt * 16 + g;
                av[mt][0] = As[m    ][ks + t];
                av[mt][1] = As[m + 8][ks + t];
                av[mt][2] = As[m    ][ks + t + 4];
                av[mt][3] = As[m + 8][ks + t + 4];
            }
            #pragma unroll
            for (int nt = 0; nt < 4; nt++) {
                int n = n0w + nt * 8 + g;
                bv[nt][0] = Bs[ks + t    ][n];
                bv[nt][1] = Bs[ks + t + 4][n];
            }
            #pragma unroll
            for (int mt = 0; mt < 4; mt++)
                #pragma unroll
                for (int nt = 0; nt < 4; nt++)
                    mma_tf32(acc[mt][nt], av[mt][0], av[mt][1], av[mt][2], av[mt][3],
                             bv[nt][0], bv[nt][1]);
        }
        __syncthreads();
    }

    #pragma unroll
    for (int mt = 0; mt < 4; mt++) {
        int r0 = row0 + m0w + mt * 16 + g;
        #pragma unroll
        for (int nt = 0; nt < 4; nt++) {
            int c0 = col0 + n0w + nt * 8 + t * 2;
            float vals[4] = {acc[mt][nt].x, acc[mt][nt].y, acc[mt][nt].z, acc[mt][nt].w};
            #pragma unroll
            for (int e = 0; e < 4; e++) {
                int r = r0 + ((e >= 2) ? 8 : 0);
                int c = c0 + (e & 1);
                if (!interior && c >= Nw) continue;
                size_t idx = (size_t)r * Nw + c;
                float v = vals[e];
                if (EPI == 1) v += Cm[idx];
                if (EPI == 2) { float sg = 1.f / (1.f + expf(-v)); v = Gb[idx] * (v * sg); }
                Cm[idx] = v;
            }
        }
    }
}

// ---------------- LayerNorm (block per row, 256 threads) ----------------
// Outputs are tf32-rounded (they only ever feed GEMM A operands).
template<int MODE>
__global__ void ln_k(const float* __restrict__ x, float* __restrict__ out,
                     const float* __restrict__ g, const float* __restrict__ bb,
                     int cols, float* __restrict__ cls)
{
    int row = blockIdx.x;
    const float* xr = x + (size_t)row * cols;
    float s = 0.f, s2 = 0.f;
    for (int c = threadIdx.x; c < cols; c += 256) { float v = xr[c]; s += v; s2 += v * v; }
    #pragma unroll
    for (int off = 16; off; off >>= 1) {
        s  += __shfl_xor_sync(0xffffffffu, s,  off);
        s2 += __shfl_xor_sync(0xffffffffu, s2, off);
    }
    __shared__ float sh[2][8];
    __shared__ float mv[2];
    int w = threadIdx.x >> 5, lane = threadIdx.x & 31;
    if (lane == 0) { sh[0][w] = s; sh[1][w] = s2; }
    __syncthreads();
    if (threadIdx.x == 0) {
        float ts = 0.f, ts2 = 0.f;
        #pragma unroll
        for (int i = 0; i < 8; i++) { ts += sh[0][i]; ts2 += sh[1][i]; }
        float m = ts / cols;
        mv[0] = m;
        mv[1] = rsqrtf(ts2 / cols - m * m + 1e-5f);
    }
    __syncthreads();
    float m = mv[0], inv = mv[1];
    float* outr = out + (size_t)row * cols;
    bool doCls = (MODE == 1) && (row % SEQ == 0);
    float* clsr = doCls ? (cls + (size_t)(row / SEQ) * cols) : nullptr;
    for (int c = threadIdx.x; c < cols; c += 256) {
        float v = (xr[c] - m) * inv * g[c] + bb[c];
        if (MODE == 2) v = v / (1.f + expf(-v));
        v = to_tf32(v);
        outr[c] = v;
        if (doCls) clsr[c] = v;
    }
}

// ---------------- q/k head LayerNorm ----------------
__global__ void qkln_k(float* __restrict__ qkv,
                       const float* __restrict__ qg, const float* __restrict__ qb,
                       const float* __restrict__ kg, const float* __restrict__ kb)
{
    int gw = blockIdx.x * 8 + (threadIdx.x >> 5);
    int lane = threadIdx.x & 31;
    if (gw >= MTOK * Hh * 2) return;
    int tok = gw / (Hh * 2);
    int rem = gw % (Hh * 2);
    int hh  = rem >> 1;
    int isK = rem & 1;
    float* p = qkv + (size_t)tok * 2304 + isK * 768 + hh * 64;
    float v0 = p[lane], v1 = p[lane + 32];
    float s = v0 + v1, s2 = v0 * v0 + v1 * v1;
    #pragma unroll
    for (int off = 16; off; off >>= 1) {
        s  += __shfl_xor_sync(0xffffffffu, s,  off);
        s2 += __shfl_xor_sync(0xffffffffu, s2, off);
    }
    float m   = s  * (1.f / 64.f);
    float inv = rsqrtf(s2 * (1.f / 64.f) - m * m + 1e-5f);
    const float* g = isK ? kg : qg;
    const float* b = isK ? kb : qb;
    float sc = isK ? 1.f : 0.125f;
    p[lane]      = ((v0 - m) * inv * g[lane]      + b[lane])      * sc;
    p[lane + 32] = ((v1 - m) * inv * g[lane + 32] + b[lane + 32]) * sc;
}

// ---------------- attention logits: attn += q @ k^T ----------------
__global__ void attn_scores_k(const float* __restrict__ qkv, float* __restrict__ attn)
{
    __shared__ float qs [SEQ][DHd];
    __shared__ float ksT[DHd][SEQ];
    int b = blockIdx.x / Hh, hh = blockIdx.x % Hh;
    for (int idx = threadIdx.x; idx < SEQ * DHd; idx += 256) {
        int i = idx >> 6, d = idx & 63;
        size_t base = (size_t)(b * SEQ + i) * 2304 + hh * 64 + d;
        qs[i][d]  = qkv[base];
        ksT[d][i] = qkv[base + 768];
    }
    __syncthreads();
    size_t obase = (size_t)blockIdx.x * (SEQ * SEQ);
    for (int oi = threadIdx.x; oi < SEQ * SEQ; oi += 256) {
        int i = oi / SEQ, j = oi - i * SEQ;
        float acc = attn[obase + oi];
        #pragma unroll
        for (int d = 0; d < DHd; d++) acc += qs[i][d] * ksT[d][j];
        attn[obase + oi] = acc;
    }
}

// ---------------- softmax over rows of 65 ----------------
__global__ void softmax65_k(float* __restrict__ attn, int rows)
{
    int r = blockIdx.x * 8 + (threadIdx.x >> 5);
    if (r >= rows) return;
    int lane = threadIdx.x & 31;
    float* p = attn + (size_t)r * SEQ;
    float v0 = p[lane], v1 = p[lane + 32];
    float v2 = (lane == 0) ? p[64] : -3.4e38f;
    float m = fmaxf(fmaxf(v0, v1), v2);
    #pragma unroll
    for (int off = 16; off; off >>= 1) m = fmaxf(m, __shfl_xor_sync(0xffffffffu, m, off));
    v0 = expf(v0 - m); v1 = expf(v1 - m);
    v2 = (lane == 0) ? expf(v2 - m) : 0.f;
    float s = v0 + v1 + v2;
    #pragma unroll
    for (int off = 16; off; off >>= 1) s += __shfl_xor_sync(0xffffffffu, s, off);
    float inv = 1.f / s;
    p[lane] = v0 * inv; p[lane + 32] = v1 * inv;
    if (lane == 0) p[64] = v2 * inv;
}

// ---------------- o = attn @ v (tf32-rounded: feeds proj GEMM A) --------
__global__ void attn_av_k(const float* __restrict__ attn, const float* __restrict__ qkv,
                          float* __restrict__ o)
{
    __shared__ float ps[SEQ][SEQ];
    __shared__ float vs[SEQ][DHd];
    int b = blockIdx.x / Hh, hh = blockIdx.x % Hh;
    size_t abase = (size_t)blockIdx.x * (SEQ * SEQ);
    for (int idx = threadIdx.x; idx < SEQ * SEQ; idx += 256)
        ps[idx / SEQ][idx % SEQ] = attn[abase + idx];
    for (int idx = threadIdx.x; idx < SEQ * DHd; idx += 256) {
        int j = idx >> 6, d = idx & 63;
        vs[j][d] = qkv[(size_t)(b * SEQ + j) * 2304 + 1536 + hh * 64 + d];
    }
    __syncthreads();
    for (int oi = threadIdx.x; oi < SEQ * DHd; oi += 256) {
        int i = oi >> 6, d = oi & 63;
        float acc = 0.f;
        #pragma unroll
        for (int j = 0; j < SEQ; j++) acc += ps[i][j] * vs[j][d];
        o[(size_t)(b * SEQ + i) * Cc + hh * 64 + d] = to_tf32(acc);
    }
}

// ---------------- host driver ----------------
extern "C" void kernel_launch(void* const* d_in, const int* in_sizes, int n_in,
                              void* d_out, int out_size)
{
    const float* x      = (const float*)d_in[0];
    const float* ln1_g  = (const float*)d_in[1];
    const float* ln1_b  = (const float*)d_in[2];
    const float* qkv_w  = (const float*)d_in[3];
    const float* proj_w = (const float*)d_in[4];
    const float* qn_g   = (const float*)d_in[5];
    const float* qn_b   = (const float*)d_in[6];
    const float* kn_g   = (const float*)d_in[7];
    const float* kn_b   = (const float*)d_in[8];
    const float* sg_w1  = (const float*)d_in[9];
    const float* sg1_g  = (const float*)d_in[10];
    const float* sg1_b  = (const float*)d_in[11];
    const float* sg_w2  = (const float*)d_in[12];
    const float* sg2_g  = (const float*)d_in[13];
    const float* sg2_b  = (const float*)d_in[14];
    const float* bias_w = (const float*)d_in[15];
    const float* ln2_g  = (const float*)d_in[16];
    const float* ln2_b  = (const float*)d_in[17];
    const float* gate_w = (const float*)d_in[18];
    const float* value_w= (const float*)d_in[19];
    const float* out_w  = (const float*)d_in[20];
    float* xout = (float*)d_out;

    float *h, *qkv, *attn, *o, *gate, *cls, *lat1, *lat2, *wtf;
    cudaGetSymbolAddress((void**)&h,    g_h);
    cudaGetSymbolAddress((void**)&qkv,  g_qkv);
    cudaGetSymbolAddress((void**)&attn, g_attn);
    cudaGetSymbolAddress((void**)&o,    g_o);
    cudaGetSymbolAddress((void**)&gate, g_gate);
    cudaGetSymbolAddress((void**)&cls,  g_cls);
    cudaGetSymbolAddress((void**)&lat1, g_lat1);
    cudaGetSymbolAddress((void**)&lat2, g_lat2);
    cudaGetSymbolAddress((void**)&wtf,  g_wtf);

    cudaMemcpyAsync(xout, x, (size_t)MTOK * Cc * sizeof(float),
                    cudaMemcpyDeviceToDevice, 0);

    // preconvert all weights to tf32 (once per replay; ~0.1 ms)
    {
        struct { const float* src; int off; int sz; } W[7] = {
            { qkv_w,  W_QKV_OFF,  W_QKV_SZ  },
            { proj_w, W_PROJ_OFF, W_PROJ_SZ },
            { sg_w1,  W_W1_OFF,   W_W1_SZ   },
            { sg_w2,  W_W2_OFF,   W_W2_SZ   },
            { gate_w, W_GATE_OFF, W_GATE_SZ },
            { value_w,W_VAL_OFF,  W_VAL_SZ  },
            { out_w,  W_OUT_OFF,  W_OUT_SZ  },
        };
        for (int i = 0; i < 7; i++) {
            int n4 = W[i].sz / 4;
            wcvt_k<<<(n4 + 255) / 256, 256>>>(W[i].src, wtf + W[i].off, n4);
        }
    }

    for (int l = 0; l < NLAYERS; l++) {
        const float* L1g = ln1_g  + (size_t)l * Cc;
        const float* L1b = ln1_b  + (size_t)l * Cc;
        const float* Wqkv= wtf + W_QKV_OFF  + (size_t)l * Cc * 3 * Cc;
        const float* Wpr = wtf + W_PROJ_OFF + (size_t)l * Cc * Cc;
        const float* Qg  = qn_g   + (size_t)l * DHd;
        const float* Qb  = qn_b   + (size_t)l * DHd;
        const float* Kg  = kn_g   + (size_t)l * DHd;
        const float* Kb  = kn_b   + (size_t)l * DHd;
        const float* W1  = wtf + W_W1_OFF   + (size_t)l * Cc * 2 * LATd;
        const float* S1g = sg1_g  + (size_t)l * 2 * LATd;
        const float* S1b = sg1_b  + (size_t)l * 2 * LATd;
        const float* W2  = wtf + W_W2_OFF   + (size_t)l * 2 * LATd * LATd * Hh;
        const float* S2g = sg2_g  + (size_t)l * LATd * Hh;
        const float* S2b = sg2_b  + (size_t)l * LATd * Hh;
        const float* Wb  = bias_w + (size_t)l * LATd * SEQ * SEQ;
        const float* L2g = ln2_g  + (size_t)l * Cc;
        const float* L2b = ln2_b  + (size_t)l * Cc;
        const float* Wg  = wtf + W_GATE_OFF + (size_t)l * Cc * 4 * Cc;
        const float* Wv  = wtf + W_VAL_OFF  + (size_t)l * Cc * 4 * Cc;
        const float* Wo  = wtf + W_OUT_OFF  + (size_t)l * 4 * Cc * Cc;

        // 1) LN1 (+ cls extraction)
        ln_k<1><<<MTOK, 256>>>(xout, h, L1g, L1b, Cc, cls);
        // 2) qkv = h @ Wqkv
        gemm_pipe_k<0><<<dim3(18, 260), 256>>>(h, Wqkv, qkv, nullptr, MTOK, 3 * Cc, Cc);
        // 3) per-head LN on q (with *scale) and k
        qkln_k<<<(MTOK * Hh * 2) / 8, 256>>>(qkv, Qg, Qb, Kg, Kb);
        // 4) cls bias path
        gemm_pipe_k<0><<<dim3(4, 4), 256>>>(cls, W1, lat1, nullptr, Bz, 2 * LATd, Cc);
        ln_k<2><<<Bz, 256>>>(lat1, lat1, S1g, S1b, 2 * LATd, nullptr);
        gemm_pipe_k<0><<<dim3(24, 4), 256>>>(lat1, W2, lat2, nullptr, Bz, LATd * Hh, 2 * LATd);
        ln_k<0><<<Bz, 256>>>(lat2, lat2, S2g, S2b, LATd * Hh, nullptr);
        // bias logits: ragged N=4225, legacy kernel (self-converting)
        gemm_tf32_k<0><<<dim3(34, 48), 256>>>(lat2, Wb, attn, nullptr, Bz * Hh, SEQ * SEQ, LATd);
        // 5) logits += q k^T ; softmax ; o = p v
        attn_scores_k<<<Bz * Hh, 256>>>(qkv, attn);
        softmax65_k<<<(Bz * Hh * SEQ) / 8, 256>>>(attn, Bz * Hh * SEQ);
        attn_av_k<<<Bz * Hh, 256>>>(attn, qkv, o);
        // 6) x += o @ Wproj
        gemm_pipe_k<1><<<dim3(6, 260), 256>>>(o, Wpr, xout, nullptr, MTOK, Cc, Cc);
        // 7) LN2
        ln_k<0><<<MTOK, 256>>>(xout, h, L2g, L2b, Cc, nullptr);
        // 8) MLP
        gemm_pipe_k<0><<<dim3(24, 260), 256>>>(h, Wg, gate, nullptr, MTOK, 4 * Cc, Cc);
        gemm_pipe_k<2><<<dim3(24, 260), 256>>>(h, Wv, gate, gate, MTOK, 4 * Cc, Cc);
        gemm_pipe_k<1><<<dim3(6, 260), 256>>>(gate, Wo, xout, nullptr, MTOK, Cc, 4 * Cc);
    }
}

// round 15
// speedup vs baseline: 2.7428x; 1.0031x over previous
#include <cuda_runtime.h>
#include <math.h>
#include <stdint.h>

// ---------------- problem constants ----------------
#define Bz      512
#define SEQ     65
#define SEQP    68                // padded row stride for attn logits
#define Cc      768
#define Hh      12
#define DHd     64
#define LATd    256
#define NLAYERS 6
#define MTOK    (Bz*SEQ)          // 33280 tokens
#define NBIAS   (35*128)          // 4480 padded bias columns (>= 65*68 = 4420)
#define ATTN_BH NBIAS             // floats per (b,h) logits block

// ---------------- scratch (device globals; no allocations) ----------------
__device__ float g_h   [MTOK*Cc];
__device__ float g_qkv [MTOK*3*Cc];
__device__ float g_attn[Bz*Hh*ATTN_BH];
__device__ float g_o   [MTOK*Cc];
__device__ float g_gate[MTOK*4*Cc];
__device__ float g_cls [Bz*Cc];
__device__ float g_lat1[Bz*2*LATd];
__device__ float g_lat2[Bz*Hh*LATd];

// tf32-preconverted weights (layout [K][N], all 6 layers, concatenated)
#define W_QKV_OFF   0
#define W_QKV_SZ    (NLAYERS*Cc*3*Cc)
#define W_PROJ_OFF  (W_QKV_OFF + W_QKV_SZ)
#define W_PROJ_SZ   (NLAYERS*Cc*Cc)
#define W_W1_OFF    (W_PROJ_OFF + W_PROJ_SZ)
#define W_W1_SZ     (NLAYERS*Cc*2*LATd)
#define W_W2_OFF    (W_W1_OFF + W_W1_SZ)
#define W_W2_SZ     (NLAYERS*2*LATd*LATd*Hh)
#define W_GATE_OFF  (W_W2_OFF + W_W2_SZ)
#define W_GATE_SZ   (NLAYERS*Cc*4*Cc)
#define W_VAL_OFF   (W_GATE_OFF + W_GATE_SZ)
#define W_VAL_SZ    (NLAYERS*Cc*4*Cc)
#define W_OUT_OFF   (W_VAL_OFF + W_VAL_SZ)
#define W_OUT_SZ    (NLAYERS*4*Cc*Cc)
#define W_BIAS_OFF  (W_OUT_OFF + W_OUT_SZ)
#define W_BIAS_SZ   (NLAYERS*LATd*NBIAS)
#define W_TOTAL     (W_BIAS_OFF + W_BIAS_SZ)
__device__ float g_wtf[W_TOTAL];

// ---------------- helpers ----------------
__device__ __forceinline__ float to_tf32(float x) {
    float r;
    asm("cvt.rna.tf32.f32 %0, %1;" : "=f"(r) : "f"(x));
    return r;
}
__device__ __forceinline__ void mma_tf32w(float4& d, const float a0, const float a1,
                                          const float a2, const float a3,
                                          const float b0, const float b1) {
    asm volatile(
        "mma.sync.aligned.m16n8k8.row.col.f32.tf32.tf32.f32 "
        "{%0,%1,%2,%3}, {%4,%5,%6,%7}, {%8,%9}, {%0,%1,%2,%3};"
        : "+f"(d.x), "+f"(d.y), "+f"(d.z), "+f"(d.w)
        : "r"(__float_as_uint(a0)), "r"(__float_as_uint(a1)),
          "r"(__float_as_uint(a2)), "r"(__float_as_uint(a3)),
          "r"(__float_as_uint(b0)), "r"(__float_as_uint(b1)));
}
__device__ __forceinline__ void cp_async16(uint32_t smem, const void* gptr) {
    asm volatile("cp.async.cg.shared.global [%0], [%1], 16;\n" :: "r"(smem), "l"(gptr));
}
__device__ __forceinline__ uint32_t smem_u32(const void* p) {
    uint32_t a;
    asm("{ .reg .u64 t; cvta.to.shared.u64 t, %1; cvt.u32.u64 %0, t; }" : "=r"(a) : "l"(p));
    return a;
}

// weight cvt: out[i] = tf32(in[i]), n4 = n/4
__global__ void wcvt_k(const float* __restrict__ in, float* __restrict__ out, int n4)
{
    int i = blockIdx.x * blockDim.x + threadIdx.x;
    if (i >= n4) return;
    float4 v = ((const float4*)in)[i];
    v.x = to_tf32(v.x); v.y = to_tf32(v.y); v.z = to_tf32(v.z); v.w = to_tf32(v.w);
    ((float4*)out)[i] = v;
}

// bias weight pad+cvt: in [256][4225] -> out [256][4480]
// out col j corresponds to logits (r=j/68, c=j%68); zero if r>=65 or c>=65
__global__ void bpad_k(const float* __restrict__ in, float* __restrict__ out)
{
    int idx = blockIdx.x * 256 + threadIdx.x;       // over 256*4480
    int k = idx / NBIAS, j = idx % NBIAS;
    int r = j / SEQP, c = j % SEQP;
    float v = 0.f;
    if (r < SEQ && c < SEQ) v = to_tf32(in[(size_t)k * (SEQ * SEQ) + r * SEQ + c]);
    out[idx] = v;
}

// ---------------- 3-stage pipelined TF32 GEMM (aligned N, pre-tf32 inputs) ----
// C[M,N] = A[M,K] @ B[K,N] row-major.  EPI=0: C=AB ; 1: C+=AB ; 2: C=tf32(Gb*silu(AB))
// M%128==0, K%16==0, N%128==0.
#define BM 128
#define BN 128
#define BKK 16
#define PA 20
#define PB 136
#define ST_A (BM*PA)                    // floats per A stage
#define ST_B (BKK*PB)                   // floats per B stage
#define PIPE_SMEM (3*(ST_A+ST_B)*4)     // 56832 bytes

template<int EPI>
__global__ __launch_bounds__(256, 2)
void gemm_pipe_k(const float* __restrict__ A, const float* __restrict__ Bw,
                 float* __restrict__ Cm, const float* __restrict__ Gb,
                 int M, int Nw, int K)
{
    extern __shared__ float dsm[];
    float* AsBase = dsm;                 // 3 stages of [BM][PA]
    float* BsBase = dsm + 3 * ST_A;      // 3 stages of [BKK][PB]

    const int tid  = threadIdx.x;
    const int row0 = blockIdx.y * BM;
    const int col0 = blockIdx.x * BN;

    const int lane = tid & 31, g = lane >> 2, t = lane & 3;
    const int wid = tid >> 5, wm = wid & 1, wn = wid >> 1;
    const int m0w = wm * 64, n0w = wn * 32;

    const int ar0 = tid >> 2,         ac0 = (tid & 3) * 4;
    const int ar1 = (tid + 256) >> 2;
    const int br0 = tid >> 5,         bc0 = (tid & 31) * 4;
    const int br1 = (tid + 256) >> 5;

    float4 acc[4][4];
    #pragma unroll
    for (int i = 0; i < 4; i++)
        #pragma unroll
        for (int j = 0; j < 4; j++) acc[i][j] = make_float4(0.f, 0.f, 0.f, 0.f);

    const uint32_t asm0 = smem_u32(AsBase);
    const uint32_t bsm0 = smem_u32(BsBase);

    auto load_stage = [&](int s, int k0) {
        uint32_t as = asm0 + (uint32_t)(s * ST_A) * 4;
        uint32_t bs = bsm0 + (uint32_t)(s * ST_B) * 4;
        cp_async16(as + (ar0 * PA + ac0) * 4, A + (size_t)(row0 + ar0) * K + k0 + ac0);
        cp_async16(as + (ar1 * PA + ac0) * 4, A + (size_t)(row0 + ar1) * K + k0 + ac0);
        cp_async16(bs + (br0 * PB + bc0) * 4, Bw + (size_t)(k0 + br0) * Nw + col0 + bc0);
        cp_async16(bs + (br1 * PB + bc0) * 4, Bw + (size_t)(k0 + br1) * Nw + col0 + bc0);
        asm volatile("cp.async.commit_group;\n");
    };

    const int nk = K / BKK;
    load_stage(0, 0);
    load_stage(1, BKK);

    for (int it = 0; it < nk; it++) {
        const int s = it % 3;
        if (it + 1 < nk) asm volatile("cp.async.wait_group 1;\n");
        else             asm volatile("cp.async.wait_group 0;\n");
        __syncthreads();                 // stage `it` visible; compute(it-1) done everywhere
        if (it + 2 < nk) load_stage((it + 2) % 3, (it + 2) * BKK);

        const float* As = AsBase + s * ST_A;
        const float* Bs = BsBase + s * ST_B;
        #pragma unroll
        for (int ks = 0; ks < BKK; ks += 8) {
            float av[4][4], bv[4][2];
            #pragma unroll
            for (int mt = 0; mt < 4; mt++) {
                int m = m0w + mt * 16 + g;
                av[mt][0] = As[m * PA + ks + t];
                av[mt][1] = As[(m + 8) * PA + ks + t];
                av[mt][2] = As[m * PA + ks + t + 4];
                av[mt][3] = As[(m + 8) * PA + ks + t + 4];
            }
            #pragma unroll
            for (int nt = 0; nt < 4; nt++) {
                int n = n0w + nt * 8 + g;
                bv[nt][0] = Bs[(ks + t) * PB + n];
                bv[nt][1] = Bs[(ks + t + 4) * PB + n];
            }
            #pragma unroll
            for (int mt = 0; mt < 4; mt++)
                #pragma unroll
                for (int nt = 0; nt < 4; nt++)
                    mma_tf32w(acc[mt][nt], av[mt][0], av[mt][1], av[mt][2], av[mt][3],
                              bv[nt][0], bv[nt][1]);
        }
    }

    #pragma unroll
    for (int mt = 0; mt < 4; mt++) {
        int r0 = row0 + m0w + mt * 16 + g;
        #pragma unroll
        for (int nt = 0; nt < 4; nt++) {
            int c0 = col0 + n0w + nt * 8 + t * 2;
            float vals[4] = {acc[mt][nt].x, acc[mt][nt].y, acc[mt][nt].z, acc[mt][nt].w};
            #pragma unroll
            for (int e = 0; e < 4; e++) {
                int r = r0 + ((e >= 2) ? 8 : 0);
                int c = c0 + (e & 1);
                size_t idx = (size_t)r * Nw + c;
                float v = vals[e];
                if (EPI == 1) v += Cm[idx];
                if (EPI == 2) {
                    float sg = 1.f / (1.f + expf(-v));
                    v = to_tf32(Gb[idx] * (v * sg));
                }
                Cm[idx] = v;
            }
        }
    }
}

// ---------------- LayerNorm (block per row, 256 threads) ----------------
// Outputs tf32-rounded (they only ever feed GEMM A operands).
template<int MODE>
__global__ void ln_k(const float* __restrict__ x, float* __restrict__ out,
                     const float* __restrict__ g, const float* __restrict__ bb,
                     int cols, float* __restrict__ cls)
{
    int row = blockIdx.x;
    const float* xr = x + (size_t)row * cols;
    float s = 0.f, s2 = 0.f;
    for (int c = threadIdx.x; c < cols; c += 256) { float v = xr[c]; s += v; s2 += v * v; }
    #pragma unroll
    for (int off = 16; off; off >>= 1) {
        s  += __shfl_xor_sync(0xffffffffu, s,  off);
        s2 += __shfl_xor_sync(0xffffffffu, s2, off);
    }
    __shared__ float sh[2][8];
    __shared__ float mv[2];
    int w = threadIdx.x >> 5, lane = threadIdx.x & 31;
    if (lane == 0) { sh[0][w] = s; sh[1][w] = s2; }
    __syncthreads();
    if (threadIdx.x == 0) {
        float ts = 0.f, ts2 = 0.f;
        #pragma unroll
        for (int i = 0; i < 8; i++) { ts += sh[0][i]; ts2 += sh[1][i]; }
        float m = ts / cols;
        mv[0] = m;
        mv[1] = rsqrtf(ts2 / cols - m * m + 1e-5f);
    }
    __syncthreads();
    float m = mv[0], inv = mv[1];
    float* outr = out + (size_t)row * cols;
    bool doCls = (MODE == 1) && (row % SEQ == 0);
    float* clsr = doCls ? (cls + (size_t)(row / SEQ) * cols) : nullptr;
    for (int c = threadIdx.x; c < cols; c += 256) {
        float v = (xr[c] - m) * inv * g[c] + bb[c];
        if (MODE == 2) v = v / (1.f + expf(-v));
        v = to_tf32(v);
        outr[c] = v;
        if (doCls) clsr[c] = v;
    }
}

// ---------------- q/k head LayerNorm ----------------
__global__ void qkln_k(float* __restrict__ qkv,
                       const float* __restrict__ qg, const float* __restrict__ qb,
                       const float* __restrict__ kg, const float* __restrict__ kb)
{
    int gw = blockIdx.x * 8 + (threadIdx.x >> 5);
    int lane = threadIdx.x & 31;
    if (gw >= MTOK * Hh * 2) return;
    int tok = gw / (Hh * 2);
    int rem = gw % (Hh * 2);
    int hh  = rem >> 1;
    int isK = rem & 1;
    float* p = qkv + (size_t)tok * 2304 + isK * 768 + hh * 64;
    float v0 = p[lane], v1 = p[lane + 32];
    float s = v0 + v1, s2 = v0 * v0 + v1 * v1;
    #pragma unroll
    for (int off = 16; off; off >>= 1) {
        s  += __shfl_xor_sync(0xffffffffu, s,  off);
        s2 += __shfl_xor_sync(0xffffffffu, s2, off);
    }
    float m   = s  * (1.f / 64.f);
    float inv = rsqrtf(s2 * (1.f / 64.f) - m * m + 1e-5f);
    const float* g = isK ? kg : qg;
    const float* b = isK ? kb : qb;
    float sc = isK ? 1.f : 0.125f;
    p[lane]      = ((v0 - m) * inv * g[lane]      + b[lane])      * sc;
    p[lane + 32] = ((v1 - m) * inv * g[lane + 32] + b[lane + 32]) * sc;
}

// ---------------- attention logits: attn += q @ k^T (padded stride 68) ----
__global__ void attn_scores_k(const float* __restrict__ qkv, float* __restrict__ attn)
{
    __shared__ float qs [SEQ][DHd];
    __shared__ float ksT[DHd][SEQ];
    int b = blockIdx.x / Hh, hh = blockIdx.x % Hh;
    for (int idx = threadIdx.x; idx < SEQ * DHd; idx += 256) {
        int i = idx >> 6, d = idx & 63;
        size_t base = (size_t)(b * SEQ + i) * 2304 + hh * 64 + d;
        qs[i][d]  = qkv[base];
        ksT[d][i] = qkv[base + 768];
    }
    __syncthreads();
    size_t obase = (size_t)blockIdx.x * ATTN_BH;
    for (int oi = threadIdx.x; oi < SEQ * SEQ; oi += 256) {
        int i = oi / SEQ, j = oi - i * SEQ;
        size_t a = obase + i * SEQP + j;
        float acc = attn[a];
        #pragma unroll
        for (int d = 0; d < DHd; d++) acc += qs[i][d] * ksT[d][j];
        attn[a] = acc;
    }
}

// ---------------- softmax over rows of 65 (stride 68) ----------------
__global__ void softmax65_k(float* __restrict__ attn, int rows)
{
    int r = blockIdx.x * 8 + (threadIdx.x >> 5);
    if (r >= rows) return;
    int lane = threadIdx.x & 31;
    float* p = attn + (size_t)(r / SEQ) * ATTN_BH + (r % SEQ) * SEQP;
    float v0 = p[lane], v1 = p[lane + 32];
    float v2 = (lane == 0) ? p[64] : -3.4e38f;
    float m = fmaxf(fmaxf(v0, v1), v2);
    #pragma unroll
    for (int off = 16; off; off >>= 1) m = fmaxf(m, __shfl_xor_sync(0xffffffffu, m, off));
    v0 = expf(v0 - m); v1 = expf(v1 - m);
    v2 = (lane == 0) ? expf(v2 - m) : 0.f;
    float s = v0 + v1 + v2;
    #pragma unroll
    for (int off = 16; off; off >>= 1) s += __shfl_xor_sync(0xffffffffu, s, off);
    float inv = 1.f / s;
    p[lane] = v0 * inv; p[lane + 32] = v1 * inv;
    if (lane == 0) p[64] = v2 * inv;
}

// ---------------- o = attn @ v (tf32-rounded; padded stride 68) ----------
__global__ void attn_av_k(const float* __restrict__ attn, const float* __restrict__ qkv,
                          float* __restrict__ o)
{
    __shared__ float ps[SEQ][SEQ];
    __shared__ float vs[SEQ][DHd];
    int b = blockIdx.x / Hh, hh = blockIdx.x % Hh;
    size_t abase = (size_t)blockIdx.x * ATTN_BH;
    for (int idx = threadIdx.x; idx < SEQ * SEQ; idx += 256) {
        int i = idx / SEQ, j = idx - i * SEQ;
        ps[i][j] = attn[abase + i * SEQP + j];
    }
    for (int idx = threadIdx.x; idx < SEQ * DHd; idx += 256) {
        int j = idx >> 6, d = idx & 63;
        vs[j][d] = qkv[(size_t)(b * SEQ + j) * 2304 + 1536 + hh * 64 + d];
    }
    __syncthreads();
    for (int oi = threadIdx.x; oi < SEQ * DHd; oi += 256) {
        int i = oi >> 6, d = oi & 63;
        float acc = 0.f;
        #pragma unroll
        for (int j = 0; j < SEQ; j++) acc += ps[i][j] * vs[j][d];
        o[(size_t)(b * SEQ + i) * Cc + hh * 64 + d] = to_tf32(acc);
    }
}

// ---------------- host driver ----------------
extern "C" void kernel_launch(void* const* d_in, const int* in_sizes, int n_in,
                              void* d_out, int out_size)
{
    const float* x      = (const float*)d_in[0];
    const float* ln1_g  = (const float*)d_in[1];
    const float* ln1_b  = (const float*)d_in[2];
    const float* qkv_w  = (const float*)d_in[3];
    const float* proj_w = (const float*)d_in[4];
    const float* qn_g   = (const float*)d_in[5];
    const float* qn_b   = (const float*)d_in[6];
    const float* kn_g   = (const float*)d_in[7];
    const float* kn_b   = (const float*)d_in[8];
    const float* sg_w1  = (const float*)d_in[9];
    const float* sg1_g  = (const float*)d_in[10];
    const float* sg1_b  = (const float*)d_in[11];
    const float* sg_w2  = (const float*)d_in[12];
    const float* sg2_g  = (const float*)d_in[13];
    const float* sg2_b  = (const float*)d_in[14];
    const float* bias_w = (const float*)d_in[15];
    const float* ln2_g  = (const float*)d_in[16];
    const float* ln2_b  = (const float*)d_in[17];
    const float* gate_w = (const float*)d_in[18];
    const float* value_w= (const float*)d_in[19];
    const float* out_w  = (const float*)d_in[20];
    float* xout = (float*)d_out;

    float *h, *qkv, *attn, *o, *gate, *cls, *lat1, *lat2, *wtf;
    cudaGetSymbolAddress((void**)&h,    g_h);
    cudaGetSymbolAddress((void**)&qkv,  g_qkv);
    cudaGetSymbolAddress((void**)&attn, g_attn);
    cudaGetSymbolAddress((void**)&o,    g_o);
    cudaGetSymbolAddress((void**)&gate, g_gate);
    cudaGetSymbolAddress((void**)&cls,  g_cls);
    cudaGetSymbolAddress((void**)&lat1, g_lat1);
    cudaGetSymbolAddress((void**)&lat2, g_lat2);
    cudaGetSymbolAddress((void**)&wtf,  g_wtf);

    // raise dynamic smem limit for the pipelined GEMM (host-side, once)
    static bool attr_done = false;
    if (!attr_done) {
        cudaFuncSetAttribute(gemm_pipe_k<0>, cudaFuncAttributeMaxDynamicSharedMemorySize, PIPE_SMEM);
        cudaFuncSetAttribute(gemm_pipe_k<1>, cudaFuncAttributeMaxDynamicSharedMemorySize, PIPE_SMEM);
        cudaFuncSetAttribute(gemm_pipe_k<2>, cudaFuncAttributeMaxDynamicSharedMemorySize, PIPE_SMEM);
        attr_done = true;
    }

    cudaMemcpyAsync(xout, x, (size_t)MTOK * Cc * sizeof(float),
                    cudaMemcpyDeviceToDevice, 0);

    // preconvert weights to tf32 (per replay)
    {
        struct { const float* src; int off; int sz; } W[7] = {
            { qkv_w,  W_QKV_OFF,  W_QKV_SZ  },
            { proj_w, W_PROJ_OFF, W_PROJ_SZ },
            { sg_w1,  W_W1_OFF,   W_W1_SZ   },
            { sg_w2,  W_W2_OFF,   W_W2_SZ   },
            { gate_w, W_GATE_OFF, W_GATE_SZ },
            { value_w,W_VAL_OFF,  W_VAL_SZ  },
            { out_w,  W_OUT_OFF,  W_OUT_SZ  },
        };
        for (int i = 0; i < 7; i++) {
            int n4 = W[i].sz / 4;
            wcvt_k<<<(n4 + 255) / 256, 256>>>(W[i].src, wtf + W[i].off, n4);
        }
        for (int l = 0; l < NLAYERS; l++)
            bpad_k<<<(LATd * NBIAS) / 256, 256>>>(bias_w + (size_t)l * LATd * SEQ * SEQ,
                                                  wtf + W_BIAS_OFF + (size_t)l * LATd * NBIAS);
    }

    for (int l = 0; l < NLAYERS; l++) {
        const float* L1g = ln1_g  + (size_t)l * Cc;
        const float* L1b = ln1_b  + (size_t)l * Cc;
        const float* Wqkv= wtf + W_QKV_OFF  + (size_t)l * Cc * 3 * Cc;
        const float* Wpr = wtf + W_PROJ_OFF + (size_t)l * Cc * Cc;
        const float* Qg  = qn_g   + (size_t)l * DHd;
        const float* Qb  = qn_b   + (size_t)l * DHd;
        const float* Kg  = kn_g   + (size_t)l * DHd;
        const float* Kb  = kn_b   + (size_t)l * DHd;
        const float* W1  = wtf + W_W1_OFF   + (size_t)l * Cc * 2 * LATd;
        const float* S1g = sg1_g  + (size_t)l * 2 * LATd;
        const float* S1b = sg1_b  + (size_t)l * 2 * LATd;
        const float* W2  = wtf + W_W2_OFF   + (size_t)l * 2 * LATd * LATd * Hh;
        const float* S2g = sg2_g  + (size_t)l * LATd * Hh;
        const float* S2b = sg2_b  + (size_t)l * LATd * Hh;
        const float* Wb  = wtf + W_BIAS_OFF + (size_t)l * LATd * NBIAS;
        const float* L2g = ln2_g  + (size_t)l * Cc;
        const float* L2b = ln2_b  + (size_t)l * Cc;
        const float* Wg  = wtf + W_GATE_OFF + (size_t)l * Cc * 4 * Cc;
        const float* Wv  = wtf + W_VAL_OFF  + (size_t)l * Cc * 4 * Cc;
        const float* Wo  = wtf + W_OUT_OFF  + (size_t)l * 4 * Cc * Cc;

        // 1) LN1 (+ cls extraction)
        ln_k<1><<<MTOK, 256>>>(xout, h, L1g, L1b, Cc, cls);
        // 2) qkv = h @ Wqkv
        gemm_pipe_k<0><<<dim3(18, 260), 256, PIPE_SMEM>>>(h, Wqkv, qkv, nullptr, MTOK, 3 * Cc, Cc);
        // 3) per-head LN on q (with *scale) and k
        qkln_k<<<(MTOK * Hh * 2) / 8, 256>>>(qkv, Qg, Qb, Kg, Kb);
        // 4) cls bias path
        gemm_pipe_k<0><<<dim3(4, 4), 256, PIPE_SMEM>>>(cls, W1, lat1, nullptr, Bz, 2 * LATd, Cc);
        ln_k<2><<<Bz, 256>>>(lat1, lat1, S1g, S1b, 2 * LATd, nullptr);
        gemm_pipe_k<0><<<dim3(24, 4), 256, PIPE_SMEM>>>(lat1, W2, lat2, nullptr, Bz, LATd * Hh, 2 * LATd);
        ln_k<0><<<Bz, 256>>>(lat2, lat2, S2g, S2b, LATd * Hh, nullptr);
        // bias logits: padded N=4480 -> fast pipelined path
        gemm_pipe_k<0><<<dim3(35, 48), 256, PIPE_SMEM>>>(lat2, Wb, attn, nullptr, Bz * Hh, NBIAS, LATd);
        // 5) logits += q k^T ; softmax ; o = p v
        attn_scores_k<<<Bz * Hh, 256>>>(qkv, attn);
        softmax65_k<<<(Bz * Hh * SEQ) / 8, 256>>>(attn, Bz * Hh * SEQ);
        attn_av_k<<<Bz * Hh, 256>>>(attn, qkv, o);
        // 6) x += o @ Wproj
        gemm_pipe_k<1><<<dim3(6, 260), 256, PIPE_SMEM>>>(o, Wpr, xout, nullptr, MTOK, Cc, Cc);
        // 7) LN2
        ln_k<0><<<MTOK, 256>>>(xout, h, L2g, L2b, Cc, nullptr);
        // 8) MLP
        gemm_pipe_k<0><<<dim3(24, 260), 256, PIPE_SMEM>>>(h, Wg, gate, nullptr, MTOK, 4 * Cc, Cc);
        gemm_pipe_k<2><<<dim3(24, 260), 256, PIPE_SMEM>>>(h, Wv, gate, gate, MTOK, 4 * Cc, Cc);
        gemm_pipe_k<1><<<dim3(6, 260), 256, PIPE_SMEM>>>(gate, Wo, xout, nullptr, MTOK, Cc, 4 * Cc);
    }
}